// round 5
// baseline (speedup 1.0000x reference)
#include <cuda_runtime.h>

// Bilinear_3882650435896: conv_transpose2d(x, w, stride=2) with block-diagonal
// w (per-channel bilinear filter) == depthwise 2x upsample.
// x: (4,256,128,128) f32 -> out: (4,256,258,258) f32.
//
// R4 -> R5: remove smem round trip. Warp per output row pair (2r, 2r+1),
// lane sweeps s = lane + 32k. Only the ALIGNED input stream is loaded
// (8 LDG.32/thread, 128B warp requests); the s-1 neighbor tap comes from
// shfl.up, with the chunk boundary (lane 0) carried from the previous
// chunk's lane 31 via a broadcast shuffle. Stores identical to R2/R4:
// float2 __stcs, lane stride 8B -> 256B contiguous warp requests.

#define C     256
#define HIN   128
#define HOUT  258

__global__ void __launch_bounds__(256)
bilinear_up_kernel(const float* __restrict__ x,
                   const float* __restrict__ w,
                   float* __restrict__ out)
{
    const int nc = blockIdx.y;            // n*C + c
    const int c  = nc & (C - 1);

    // Filter taps: warp-uniform __ldg (L1-hit broadcast), no smem/sync.
    const float* __restrict__ wc = w + (size_t)c * (C + 1) * 16;
    float f[16];
#pragma unroll
    for (int i = 0; i < 16; i++) f[i] = __ldg(wc + i);

    const int warp = threadIdx.x >> 5;
    const int lane = threadIdx.x & 31;
    const int r    = blockIdx.x * 8 + warp;   // row-pair index, 0..128
    if (r > HIN) return;

    const bool rm = (r >= 1);
    const bool rv = (r < HIN);
    const float* __restrict__ xr0 =
        x + (size_t)nc * (HIN * HIN) + (size_t)(r - 1) * HIN;  // row r-1
    const float* __restrict__ xr1 = xr0 + HIN;                 // row r

    // Front-batched aligned loads only: s = lane + 32k, k = 0..3.
    float a0[4], a1[4];
#pragma unroll
    for (int k = 0; k < 4; k++) {
        const int s = lane + 32 * k;
        a0[k] = rm ? __ldg(xr0 + s) : 0.f;
        a1[k] = rv ? __ldg(xr1 + s) : 0.f;
    }

    float* __restrict__ o0 =
        out + (size_t)nc * (HOUT * HOUT) + (size_t)(2 * r) * HOUT;
    float* __restrict__ o1 = o0 + HOUT;

    float carry0 = 0.f, carry1 = 0.f;     // x[.][s-1] for lane 0 of chunk k
#pragma unroll
    for (int k = 0; k < 4; k++) {
        const int s = lane + 32 * k;
        // Neighbor tap x[.][s-1]: shfl.up within chunk; lane 0 takes the
        // previous chunk's lane-31 value (0 for k=0, i.e. s=0).
        float x00 = __shfl_up_sync(0xffffffffu, a0[k], 1);
        float x10 = __shfl_up_sync(0xffffffffu, a1[k], 1);
        if (lane == 0) { x00 = carry0; x10 = carry1; }
        carry0 = __shfl_sync(0xffffffffu, a0[k], 31);
        carry1 = __shfl_sync(0xffffffffu, a1[k], 31);

        const float x01 = a0[k], x11 = a1[k];
        const float v00 = x11 * f[0] + x10 * f[2]  + x01 * f[8]  + x00 * f[10];
        const float v01 = x11 * f[1] + x10 * f[3]  + x01 * f[9]  + x00 * f[11];
        const float v10 = x11 * f[4] + x10 * f[6]  + x01 * f[12] + x00 * f[14];
        const float v11 = x11 * f[5] + x10 * f[7]  + x01 * f[13] + x00 * f[15];
        __stcs(reinterpret_cast<float2*>(o0 + 2 * s), make_float2(v00, v01));
        __stcs(reinterpret_cast<float2*>(o1 + 2 * s), make_float2(v10, v11));
    }

    // Tail (output cols 256,257): only input col 127 = lane 31's a[3].
    if (lane == 31) {
        const float x00 = a0[3], x10 = a1[3];
        __stcs(reinterpret_cast<float2*>(o0 + 2 * HIN),
               make_float2(x10 * f[2] + x00 * f[10], x10 * f[3] + x00 * f[11]));
        __stcs(reinterpret_cast<float2*>(o1 + 2 * HIN),
               make_float2(x10 * f[6] + x00 * f[14], x10 * f[7] + x00 * f[15]));
    }
}

extern "C" void kernel_launch(void* const* d_in, const int* in_sizes, int n_in,
                              void* d_out, int out_size)
{
    const float* x = (const float*)d_in[0];   // (4,256,128,128)
    const float* w = (const float*)d_in[1];   // (256,256,4,4)
    float* out = (float*)d_out;               // (4,256,258,258)

    dim3 block(256);
    dim3 grid((HIN + 1 + 7) / 8, 4 * C);      // (17, 1024)
    bilinear_up_kernel<<<grid, block>>>(x, w, out);
}

// round 6
// speedup vs baseline: 1.0102x; 1.0102x over previous
#include <cuda_runtime.h>
#include <cstdint>

// Bilinear_3882650435896: conv_transpose2d(x, w, stride=2) with block-diagonal
// w (per-channel bilinear filter) == depthwise 2x upsample.
// x: (4,256,128,128) f32 -> out: (4,256,258,258) f32.
//
// R4 -> R6: keep R4's smem-staged compute (warp per row pair, s=lane+32k,
// occ-8 / 32-reg shape) but route the OUTPUT through smem + cp.async.bulk
// (1D bulk shared->global). A row pair (2064B) is contiguous and 16B-aligned
// in gmem, so one bulk op per warp replaces 9 straddling STG instructions:
// stores leave via the async engine as whole lines, L1 store wavefronts gone.

#define C     256
#define HIN   128
#define HOUT  258
#define NROWS 9          // input rows staged per block
#define SROW  136        // smem input row stride in words (4 pad + 128 + 4)
#define OBUF  (2 * HOUT) // 516 floats = 2064 B per warp output buffer

__device__ __forceinline__ uint32_t smem_u32(const void* p) {
    uint32_t a;
    asm("{ .reg .u64 t; cvta.to.shared.u64 t, %1; cvt.u32.u64 %0, t; }"
        : "=r"(a) : "l"(p));
    return a;
}

__global__ void __launch_bounds__(256)
bilinear_up_kernel(const float* __restrict__ x,
                   const float* __restrict__ w,
                   float* __restrict__ out)
{
    const int nc = blockIdx.y;            // n*C + c
    const int c  = nc & (C - 1);
    const int R  = blockIdx.x * 8;        // first row-pair index of this block

    __shared__ float fs[16];
    __shared__ float tile[NROWS * SROW];                 // 4.9 KB input stage
    __shared__ __align__(16) float obuf[8][OBUF];        // 16.5 KB output stage

    if (threadIdx.x < 16)
        fs[threadIdx.x] = w[(size_t)c * (C + 1) * 16 + threadIdx.x];
    if (threadIdx.x < NROWS * 4) {        // zero 4-word left pad per row
        const int row = threadIdx.x >> 2;
        tile[row * SROW + (threadIdx.x & 3)] = 0.f;
    }

    // Stage 9 input rows as float4: 9*32 = 288 vectors across 256 threads.
    const float4* __restrict__ x4 =
        reinterpret_cast<const float4*>(x + (size_t)nc * (HIN * HIN));
    const float4 z4 = make_float4(0.f, 0.f, 0.f, 0.f);
#pragma unroll
    for (int i = threadIdx.x; i < NROWS * 32; i += 256) {
        const int row = i >> 5;
        const int j   = i & 31;
        const int g   = R - 1 + row;
        const float4 v = (g >= 0 && g < HIN) ? __ldg(&x4[g * 32 + j]) : z4;
        *reinterpret_cast<float4*>(&tile[row * SROW + 4 + 4 * j]) = v;
    }
    __syncthreads();

    const float f0 = fs[0],  f1 = fs[1],  f2 = fs[2],  f3 = fs[3];
    const float f4 = fs[4],  f5 = fs[5],  f6 = fs[6],  f7 = fs[7];
    const float f8 = fs[8],  f9 = fs[9],  f10 = fs[10], f11 = fs[11];
    const float f12 = fs[12], f13 = fs[13], f14 = fs[14], f15 = fs[15];

    const int warp = threadIdx.x >> 5;
    const int lane = threadIdx.x & 31;
    const int r    = R + warp;            // row-pair index, valid if <= 128
    if (r > HIN) return;

    const float* __restrict__ sm0 = &tile[warp * SROW];        // input row r-1
    const float* __restrict__ sm1 = &tile[(warp + 1) * SROW];  // input row r
    float* __restrict__ b0 = obuf[warp];          // output row 2r   (516 f)
    float* __restrict__ b1 = obuf[warp] + HOUT;   // output row 2r+1

#pragma unroll
    for (int k = 0; k < 4; k++) {
        const int s = lane + 32 * k;
        const float x00 = sm0[s + 3], x01 = sm0[s + 4];
        const float x10 = sm1[s + 3], x11 = sm1[s + 4];
        const float v00 = x11 * f0 + x10 * f2  + x01 * f8  + x00 * f10;
        const float v01 = x11 * f1 + x10 * f3  + x01 * f9  + x00 * f11;
        const float v10 = x11 * f4 + x10 * f6  + x01 * f12 + x00 * f14;
        const float v11 = x11 * f5 + x10 * f7  + x01 * f13 + x00 * f15;
        *reinterpret_cast<float2*>(b0 + 2 * s) = make_float2(v00, v01);
        *reinterpret_cast<float2*>(b1 + 2 * s) = make_float2(v10, v11);
    }
    if (lane == 31) {                     // tail cols 256,257 (input col 127)
        const float x00 = sm0[131], x10 = sm1[131];
        *reinterpret_cast<float2*>(b0 + 2 * HIN) =
            make_float2(x10 * f2 + x00 * f10, x10 * f3 + x00 * f11);
        *reinterpret_cast<float2*>(b1 + 2 * HIN) =
            make_float2(x10 * f6 + x00 * f14, x10 * f7 + x00 * f15);
    }

    __syncwarp();
    if (lane == 0) {
        // Make generic-proxy STS visible to the async (bulk) proxy.
        asm volatile("fence.proxy.async.shared::cta;" ::: "memory");
        float* gdst = out + (size_t)nc * (HOUT * HOUT) + (size_t)r * OBUF;
        const uint32_t saddr = smem_u32(obuf[warp]);
        asm volatile(
            "cp.async.bulk.global.shared::cta.bulk_group [%0], [%1], %2;"
            :: "l"(gdst), "r"(saddr), "n"(OBUF * 4) : "memory");
        asm volatile("cp.async.bulk.commit_group;" ::: "memory");
        asm volatile("cp.async.bulk.wait_group 0;" ::: "memory");
    }
}

extern "C" void kernel_launch(void* const* d_in, const int* in_sizes, int n_in,
                              void* d_out, int out_size)
{
    const float* x = (const float*)d_in[0];   // (4,256,128,128)
    const float* w = (const float*)d_in[1];   // (256,256,4,4)
    float* out = (float*)d_out;               // (4,256,258,258)

    dim3 block(256);
    dim3 grid((HIN + 1 + 7) / 8, 4 * C);      // (17, 1024)
    bilinear_up_kernel<<<grid, block>>>(x, w, out);
}

// round 7
// speedup vs baseline: 1.1054x; 1.0942x over previous
#include <cuda_runtime.h>

// Bilinear_3882650435896: conv_transpose2d(x, w, stride=2) with block-diagonal
// w (per-channel bilinear filter) == depthwise 2x upsample.
// x: (4,256,128,128) f32 -> out: (4,256,258,258) f32.
//
// R4 -> R7: same proven skeleton (smem-staged input rows, warp per row pair,
// lane sweeps s=lane+32k, float2 __stcs stores = 256B contiguous warp
// requests), but each block now covers 16 row pairs (each warp does pairs
// r and r+8), staging 17 input rows once. Halves staging + sync overhead per
// output and doubles independent memory ops in flight per thread.

#define C     256
#define HIN   128
#define HOUT  258
#define NROWS 17         // input rows staged per block (R-1 .. R+15)
#define SROW  136        // smem row stride in words (4 left-pad + 128 + 4)
#define PAIRS 16         // row pairs per block

__global__ void __launch_bounds__(256)
bilinear_up_kernel(const float* __restrict__ x,
                   const float* __restrict__ w,
                   float* __restrict__ out)
{
    const int nc = blockIdx.y;            // n*C + c
    const int c  = nc & (C - 1);
    const int R  = blockIdx.x * PAIRS;    // first row-pair index of this block

    __shared__ float fs[16];
    __shared__ float tile[NROWS * SROW];  // 2312 words = 9.25 KB

    if (threadIdx.x < 16)
        fs[threadIdx.x] = w[(size_t)c * (C + 1) * 16 + threadIdx.x];
    if (threadIdx.x < NROWS * 4) {        // zero 4-word left pad per row
        const int row = threadIdx.x >> 2;
        tile[row * SROW + (threadIdx.x & 3)] = 0.f;
    }

    // Stage 17 input rows as float4: 17*32 = 544 vectors across 256 threads.
    const float4* __restrict__ x4 =
        reinterpret_cast<const float4*>(x + (size_t)nc * (HIN * HIN));
    const float4 z4 = make_float4(0.f, 0.f, 0.f, 0.f);
#pragma unroll
    for (int i = threadIdx.x; i < NROWS * 32; i += 256) {
        const int row = i >> 5;           // 0..16
        const int j   = i & 31;           // float4 index within row
        const int g   = R - 1 + row;      // global input row
        const float4 v = (g >= 0 && g < HIN) ? __ldg(&x4[g * 32 + j]) : z4;
        *reinterpret_cast<float4*>(&tile[row * SROW + 4 + 4 * j]) = v;
    }
    __syncthreads();

    const float f0 = fs[0],  f1 = fs[1],  f2 = fs[2],  f3 = fs[3];
    const float f4 = fs[4],  f5 = fs[5],  f6 = fs[6],  f7 = fs[7];
    const float f8 = fs[8],  f9 = fs[9],  f10 = fs[10], f11 = fs[11];
    const float f12 = fs[12], f13 = fs[13], f14 = fs[14], f15 = fs[15];

    const int warp = threadIdx.x >> 5;
    const int lane = threadIdx.x & 31;

#pragma unroll
    for (int p = 0; p < 2; p++) {
        const int tr = warp + 8 * p;      // tile row of input row r-1
        const int r  = R + tr;            // row-pair index, valid if <= 128
        if (r > HIN) continue;

        const float* __restrict__ sm0 = &tile[tr * SROW];        // row r-1
        const float* __restrict__ sm1 = &tile[(tr + 1) * SROW];  // row r

        float* __restrict__ o0 =
            out + (size_t)nc * (HOUT * HOUT) + (size_t)(2 * r) * HOUT;
        float* __restrict__ o1 = o0 + HOUT;

#pragma unroll
        for (int k = 0; k < 4; k++) {
            const int s = lane + 32 * k;
            const float x00 = sm0[s + 3], x01 = sm0[s + 4];
            const float x10 = sm1[s + 3], x11 = sm1[s + 4];
            const float v00 = x11 * f0 + x10 * f2  + x01 * f8  + x00 * f10;
            const float v01 = x11 * f1 + x10 * f3  + x01 * f9  + x00 * f11;
            const float v10 = x11 * f4 + x10 * f6  + x01 * f12 + x00 * f14;
            const float v11 = x11 * f5 + x10 * f7  + x01 * f13 + x00 * f15;
            __stcs(reinterpret_cast<float2*>(o0 + 2 * s), make_float2(v00, v01));
            __stcs(reinterpret_cast<float2*>(o1 + 2 * s), make_float2(v10, v11));
        }

        // Tail (output cols 256,257): only input col 127 contributes.
        if (lane == 31) {
            const float x00 = sm0[131], x10 = sm1[131];
            __stcs(reinterpret_cast<float2*>(o0 + 2 * HIN),
                   make_float2(x10 * f2 + x00 * f10, x10 * f3 + x00 * f11));
            __stcs(reinterpret_cast<float2*>(o1 + 2 * HIN),
                   make_float2(x10 * f6 + x00 * f14, x10 * f7 + x00 * f15));
        }
    }
}

extern "C" void kernel_launch(void* const* d_in, const int* in_sizes, int n_in,
                              void* d_out, int out_size)
{
    const float* x = (const float*)d_in[0];   // (4,256,128,128)
    const float* w = (const float*)d_in[1];   // (256,256,4,4)
    float* out = (float*)d_out;               // (4,256,258,258)

    dim3 block(256);
    dim3 grid((HIN + 1 + PAIRS - 1) / PAIRS, 4 * C);   // (9, 1024)
    bilinear_up_kernel<<<grid, block>>>(x, w, out);
}

// round 8
// speedup vs baseline: 1.1325x; 1.0246x over previous
#include <cuda_runtime.h>

// Bilinear_3882650435896: conv_transpose2d(x, w, stride=2) with block-diagonal
// w (per-channel bilinear filter) == depthwise 2x upsample.
// x: (4,256,128,128) f32 -> out: (4,256,258,258) f32.
//
// R7 -> R8: (a) exploit filter separability f[kh][kw] = g[kh]*g[kw]
// (recovered at runtime: g1=sqrt(f11), g[i]=f[i][1]/g1) -> 4 filter regs
// instead of 16; (b) front-batch all 16 LDS of a row pair into registers
// before computing (MLP 16, hides the 29-cyc LDS latency). Store mapping
// unchanged from R4/R7: float2 __stcs, 256B contiguous warp requests.

#define C     256
#define HIN   128
#define HOUT  258
#define NROWS 17         // input rows staged per block (R-1 .. R+15)
#define SROW  136        // smem row stride in words (4 left-pad + 128 + 4)
#define PAIRS 16         // row pairs per block

__global__ void __launch_bounds__(256)
bilinear_up_kernel(const float* __restrict__ x,
                   const float* __restrict__ w,
                   float* __restrict__ out)
{
    const int nc = blockIdx.y;            // n*C + c
    const int c  = nc & (C - 1);
    const int R  = blockIdx.x * PAIRS;    // first row-pair index of this block

    __shared__ float tile[NROWS * SROW];  // 2312 words = 9.25 KB

    if (threadIdx.x < NROWS * 4) {        // zero 4-word left pad per row
        const int row = threadIdx.x >> 2;
        tile[row * SROW + (threadIdx.x & 3)] = 0.f;
    }

    // Stage 17 input rows as float4: 17*32 = 544 vectors across 256 threads.
    const float4* __restrict__ x4 =
        reinterpret_cast<const float4*>(x + (size_t)nc * (HIN * HIN));
    const float4 z4 = make_float4(0.f, 0.f, 0.f, 0.f);
#pragma unroll
    for (int i = threadIdx.x; i < NROWS * 32; i += 256) {
        const int row = i >> 5;
        const int j   = i & 31;
        const int g   = R - 1 + row;
        const float4 v = (g >= 0 && g < HIN) ? __ldg(&x4[g * 32 + j]) : z4;
        *reinterpret_cast<float4*>(&tile[row * SROW + 4 + 4 * j]) = v;
    }

    // Separable filter recovery (warp-uniform __ldg, exact for bilinear taps):
    // f[kh][kw] = g[kh]*g[kw]; g1 = sqrt(f[1][1]); g[i] = f[i][1]/g1.
    const float* __restrict__ wc = w + (size_t)c * (C + 1) * 16;
    const float g1 = sqrtf(__ldg(wc + 5));     // f[1][1]
    const float g0 = __ldg(wc + 1)  / g1;      // f[0][1]
    const float g2 = __ldg(wc + 9)  / g1;      // f[2][1]
    const float g3 = __ldg(wc + 13) / g1;      // f[3][1]

    __syncthreads();

    const int warp = threadIdx.x >> 5;
    const int lane = threadIdx.x & 31;

#pragma unroll
    for (int p = 0; p < 2; p++) {
        const int tr = warp + 8 * p;      // tile row of input row r-1
        const int r  = R + tr;            // row-pair index, valid if <= 128
        if (r > HIN) continue;

        const float* __restrict__ sm0 = &tile[tr * SROW];        // row r-1
        const float* __restrict__ sm1 = &tile[(tr + 1) * SROW];  // row r

        // Front-batched: all 16 smem reads for this pair before any compute.
        float d00[4], d01[4], d10[4], d11[4];
#pragma unroll
        for (int k = 0; k < 4; k++) {
            const int s = lane + 32 * k;
            d00[k] = sm0[s + 3];  d01[k] = sm0[s + 4];
            d10[k] = sm1[s + 3];  d11[k] = sm1[s + 4];
        }

        float* __restrict__ o0 =
            out + (size_t)nc * (HOUT * HOUT) + (size_t)(2 * r) * HOUT;
        float* __restrict__ o1 = o0 + HOUT;

#pragma unroll
        for (int k = 0; k < 4; k++) {
            const int s = lane + 32 * k;
            // Column combos (kw): col s -> g0/g1, col s-1 -> g2/g3.
            const float P  = g0 * d11[k] + g2 * d10[k];   // row r,   even col
            const float Pp = g1 * d11[k] + g3 * d10[k];   // row r,   odd col
            const float Q  = g0 * d01[k] + g2 * d00[k];   // row r-1, even col
            const float Qp = g1 * d01[k] + g3 * d00[k];   // row r-1, odd col
            // Row combos (kh): row 2r -> g0/g2, row 2r+1 -> g1/g3.
            const float v00 = g0 * P  + g2 * Q;
            const float v01 = g0 * Pp + g2 * Qp;
            const float v10 = g1 * P  + g3 * Q;
            const float v11 = g1 * Pp + g3 * Qp;
            __stcs(reinterpret_cast<float2*>(o0 + 2 * s), make_float2(v00, v01));
            __stcs(reinterpret_cast<float2*>(o1 + 2 * s), make_float2(v10, v11));
        }

        // Tail (output cols 256,257): only input col 127 (= d?0[3] of lane31).
        if (lane == 31) {
            const float x00 = d00[3] * 0.f + sm0[131];   // keep simple: reload
            const float x10 = sm1[131];
            const float Qt = g2 * x00, Pt = g2 * x10;    // col 127 -> kw=2/3
            const float Qt3 = g3 * x00, Pt3 = g3 * x10;
            __stcs(reinterpret_cast<float2*>(o0 + 2 * HIN),
                   make_float2(g0 * Pt + g2 * Qt, g0 * Pt3 + g2 * Qt3));
            __stcs(reinterpret_cast<float2*>(o1 + 2 * HIN),
                   make_float2(g1 * Pt + g3 * Qt, g1 * Pt3 + g3 * Qt3));
        }
    }
}

extern "C" void kernel_launch(void* const* d_in, const int* in_sizes, int n_in,
                              void* d_out, int out_size)
{
    const float* x = (const float*)d_in[0];   // (4,256,128,128)
    const float* w = (const float*)d_in[1];   // (256,256,4,4)
    float* out = (float*)d_out;               // (4,256,258,258)

    dim3 block(256);
    dim3 grid((HIN + 1 + PAIRS - 1) / PAIRS, 4 * C);   // (9, 1024)
    bilinear_up_kernel<<<grid, block>>>(x, w, out);
}